// round 14
// baseline (speedup 1.0000x reference)
#include <cuda_runtime.h>
#include <cuda_fp16.h>
#include <cstdint>
#include <math.h>

#define NTOK 16384
#define DIM  4096
#define NE   64
#define BT   64                   // tokens per CTA (M): 4 m16 stripes
#define KT   32                   // K per chunk (2 k16 halves, split across warps)
#define NCH  (DIM / KT)           // 128
#define NBUF 4
#define NTHR 512
#define ARSTR 80                  // A f16 row stride in bytes (32 f16 = 64B + 16B pad)
#define AARRB (BT * ARSTR)        // 5120 per array (hi / lo)
#define ABYTES (2 * AARRB)        // 10240
// packed W tile: [arr 2][nhalf 2][qid 8][kpair 16 x 4B x 4nt + 64B pad]
#define WQSTR  320
#define WARRB  (2 * 8 * WQSTR)    // 5120 per array
#define WBYTES (2 * WARRB)        // 10240 per chunk
#define BUFB   (ABYTES + WBYTES)  // 20480
#define SMEM_DYN (NBUF * BUFB)    // 81920  (x2 CTAs = 160KB/SM)
#define SCSTR 66

static __device__ __forceinline__ uint32_t smem_u32(const void* p) {
    uint32_t a;
    asm("{ .reg .u64 t; cvta.to.shared.u64 t, %1; cvt.u32.u64 %0, t; }"
        : "=r"(a) : "l"(p));
    return a;
}
static __device__ __forceinline__ void cp16(uint32_t dst, const void* src) {
    asm volatile("cp.async.cg.shared.global [%0], [%1], 16;"
                 :: "r"(dst), "l"(src) : "memory");
}
#define CP_COMMIT() asm volatile("cp.async.commit_group;" ::: "memory")
#define CP_WAIT(n)  asm volatile("cp.async.wait_group %0;" :: "n"(n) : "memory")

// split: hi = rz-f16 pack (== mantissa-mask in normal range), lo = rz-f16(x - mask(x)).
static __device__ __forceinline__ void split_pair(float f0, float f1,
                                                  uint32_t& hi2, uint32_t& lo2) {
    asm("cvt.rz.f16x2.f32 %0, %1, %2;" : "=r"(hi2) : "f"(f1), "f"(f0));
    const float m0 = __uint_as_float(__float_as_uint(f0) & 0xffffe000u);
    const float m1 = __uint_as_float(__float_as_uint(f1) & 0xffffe000u);
    const float r0 = f0 - m0, r1 = f1 - m1;
    asm("cvt.rz.f16x2.f32 %0, %1, %2;" : "=r"(lo2) : "f"(r1), "f"(r0));
}
static __device__ __forceinline__ void mma16(float* c, const uint32_t* a,
                                             uint32_t b0, uint32_t b1) {
    asm volatile(
        "mma.sync.aligned.m16n8k16.row.col.f32.f16.f16.f32 "
        "{%0,%1,%2,%3}, {%4,%5,%6,%7}, {%8,%9}, {%0,%1,%2,%3};"
        : "+f"(c[0]), "+f"(c[1]), "+f"(c[2]), "+f"(c[3])
        : "r"(a[0]), "r"(a[1]), "r"(a[2]), "r"(a[3]), "r"(b0), "r"(b1));
}
static __device__ __forceinline__ void ldmx4(uint32_t* r, uint32_t addr) {
    asm volatile("ldmatrix.sync.aligned.m8n8.x4.shared.b16 {%0,%1,%2,%3}, [%4];"
                 : "=r"(r[0]), "=r"(r[1]), "=r"(r[2]), "=r"(r[3]) : "r"(addr));
}
static __device__ __forceinline__ void sts8(uint32_t addr, uint32_t v0, uint32_t v1) {
    asm volatile("st.shared.v2.b32 [%0], {%1, %2};" :: "r"(addr), "r"(v0), "r"(v1) : "memory");
}

// Packed, pre-split W (same layout as R12/13): per chunk [hi|lo][nhalf][qid][kpair].
__device__ __align__(16) char g_wpack[NCH * WBYTES];

__global__ void pack_w_kernel(const float* __restrict__ W) {
    const int i = blockIdx.x * blockDim.x + threadIdx.x;   // 131072
    if (i >= NE * NCH * 16) return;
    const int kpair = i & 15;
    const int chunk = (i >> 4) & (NCH - 1);
    const int e     = i >> 11;
    const int nhalf = e >> 5, rem = e & 31, nt = rem >> 3, qid = rem & 7;
    const int k0 = chunk * KT + kpair * 2;
    const float w0 = W[(size_t)e * DIM + k0];
    const float w1 = W[(size_t)e * DIM + k0 + 1];
    const __half h0 = __float2half_rn(w0), h1 = __float2half_rn(w1);
    const __half l0 = __float2half_rn(w0 - __half2float(h0));
    const __half l1 = __float2half_rn(w1 - __half2float(h1));
    const uint32_t hi = ((uint32_t)__half_as_ushort(h1) << 16) | __half_as_ushort(h0);
    const uint32_t lo = ((uint32_t)__half_as_ushort(l1) << 16) | __half_as_ushort(l0);
    const uint32_t base = (uint32_t)chunk * WBYTES
                        + (uint32_t)(nhalf * 8 + qid) * WQSTR + kpair * 16 + nt * 4;
    *(uint32_t*)(g_wpack + base)         = hi;
    *(uint32_t*)(g_wpack + base + WARRB) = lo;
}

__global__ __launch_bounds__(NTHR, 2)
void gating_mma(const float* __restrict__ X, const float* __restrict__ B,
                float* __restrict__ out, int voff)
{
    extern __shared__ char smem[];
    const int tid    = threadIdx.x;
    const int wid    = tid >> 5;
    const int lane   = tid & 31;
    const int qid    = lane >> 2;
    const int qt     = lane & 3;
    const int stripe = wid & 3;          // m16 stripe 0..3
    const int nhalf  = (wid >> 2) & 1;   // experts [nhalf*32, +32)
    const int khalf  = wid >> 3;         // k16 half within each chunk
    const int token0 = blockIdx.x * BT;

    const uint32_t sbase = smem_u32(smem);

    // ---- producers ----
    // A: 64 rows x 8 segs(4 floats) -> 1 LDG.128 + split + 2 STS.64 per thread
    const int ar = tid >> 3, as = tid & 7;
    const float4* agp = (const float4*)(X + (size_t)(token0 + ar) * DIM + as * 4);
    const uint32_t asts = sbase + (uint32_t)ar * ARSTR + as * 8;
    // W: 10240 B = 640 cp16 -> 1 per thread + 1 for tid<128
    const char* wsrc0 = g_wpack + tid * 16;
    const char* wsrc1 = g_wpack + 8192 + tid * 16;
    const uint32_t woff0 = ABYTES + tid * 16;
    const uint32_t woff1 = ABYTES + 8192 + tid * 16;

    auto ldg_a = [&](int c, float4& r) { r = agp[c * (KT / 4)]; };
    auto sts_a = [&](int c, const float4& r) {
        const uint32_t bb = asts + (uint32_t)(c & (NBUF - 1)) * BUFB;
        uint32_t h0, l0, h1, l1;
        split_pair(r.x, r.y, h0, l0);
        split_pair(r.z, r.w, h1, l1);
        sts8(bb, h0, h1);
        sts8(bb + AARRB, l0, l1);
    };
    auto cp_w = [&](int c) {
        const uint32_t bb = sbase + (uint32_t)(c & (NBUF - 1)) * BUFB;
        cp16(bb + woff0, wsrc0 + (size_t)c * WBYTES);
        if (tid < 128) cp16(bb + woff1, wsrc1 + (size_t)c * WBYTES);
    };

    float acc[4][4];
    #pragma unroll
    for (int nt = 0; nt < 4; nt++)
        #pragma unroll
        for (int j = 0; j < 4; j++) acc[nt][j] = 0.f;

    float4 xr[2];
    ldg_a(0, xr[0]);
    ldg_a(1, xr[1]);
    sts_a(0, xr[0]);
    cp_w(0); CP_COMMIT();
    cp_w(1); CP_COMMIT();
    cp_w(2); CP_COMMIT();

    // ldmatrix lane address (relative to buffer base): four 8x8 mats of m16xk16
    const int lm   = lane >> 3, lr = lane & 7;
    const uint32_t almoff = (uint32_t)(stripe * 16 + (lm & 1) * 8 + lr) * ARSTR
                          + khalf * 32 + (lm >> 1) * 16;
    const uint32_t wlane = ABYTES + (uint32_t)(nhalf * 8 + qid) * WQSTR
                         + (khalf * 8 + qt) * 16;

    #pragma unroll 1
    for (int c = 0; c < NCH; c++) {
        CP_WAIT(2);
        __syncthreads();

        const uint32_t bb = sbase + (uint32_t)(c & (NBUF - 1)) * BUFB;

        uint32_t ah[4], al[4];
        ldmx4(ah, bb + almoff);
        ldmx4(al, bb + almoff + AARRB);

        const char* Wp = smem + (c & (NBUF - 1)) * BUFB + ABYTES - ABYTES; // silence
        const uint4 vh0 = *(const uint4*)(smem + (bb - sbase) + wlane);
        const uint4 vh1 = *(const uint4*)(smem + (bb - sbase) + wlane + 64);
        const uint4 vl0 = *(const uint4*)(smem + (bb - sbase) + wlane + WARRB);
        const uint4 vl1 = *(const uint4*)(smem + (bb - sbase) + wlane + WARRB + 64);
        const uint32_t bh0[4] = {vh0.x, vh0.y, vh0.z, vh0.w};
        const uint32_t bh1[4] = {vh1.x, vh1.y, vh1.z, vh1.w};
        const uint32_t bl0[4] = {vl0.x, vl0.y, vl0.z, vl0.w};
        const uint32_t bl1[4] = {vl1.x, vl1.y, vl1.z, vl1.w};
        (void)Wp;

        #pragma unroll
        for (int nt = 0; nt < 4; nt++) mma16(acc[nt], ah, bh0[nt], bh1[nt]); // Ah*Bh
        #pragma unroll
        for (int nt = 0; nt < 4; nt++) mma16(acc[nt], ah, bl0[nt], bl1[nt]); // Ah*Bl
        #pragma unroll
        for (int nt = 0; nt < 4; nt++) mma16(acc[nt], al, bh0[nt], bh1[nt]); // Al*Bh

        // stage A one chunk ahead; refill register two ahead
        if (c + 1 < NCH) sts_a(c + 1, xr[(c + 1) & 1]);
        if (c + 2 < NCH) ldg_a(c + 2, xr[c & 1]);
        if (c + 3 < NCH) cp_w(c + 3);
        CP_COMMIT();   // uniform group accounting
    }

    CP_WAIT(0);
    __syncthreads();

    // ---- scores -> two smem banks (khalf partials), bias fused into bank 0 ----
    float* SC = (float*)smem;
    {
        float* SCk = SC + khalf * (BT * SCSTR);
        const int r0 = stripe * 16 + qid, r1 = r0 + 8;
        #pragma unroll
        for (int nt = 0; nt < 4; nt++) {
            const int cb = nhalf * 32 + nt * 8 + qt * 2;
            const float b0 = khalf ? 0.f : __ldg(B + cb);
            const float b1 = khalf ? 0.f : __ldg(B + cb + 1);
            *(float2*)(SCk + r0 * SCSTR + cb) = make_float2(acc[nt][0] + b0, acc[nt][1] + b1);
            *(float2*)(SCk + r1 * SCSTR + cb) = make_float2(acc[nt][2] + b0, acc[nt][3] + b1);
        }
    }
    __syncthreads();

    if (tid < BT) {
        const float* row0 = SC + tid * SCSTR;
        const float* row1 = row0 + BT * SCSTR;

        float sc[NE];
        #pragma unroll
        for (int e = 0; e < NE; e++) sc[e] = row0[e] + row1[e];

        float m = sc[0];
        #pragma unroll
        for (int e = 1; e < NE; e++) m = fmaxf(m, sc[e]);

        float se = 0.f;
        #pragma unroll
        for (int e = 0; e < NE; e++) se += __expf(sc[e] - m);

        float v1 = -1e30f, v2 = -1e30f; int i1 = -1, i2 = -1;
        #pragma unroll
        for (int e = 0; e < NE; e++) {
            const float s = sc[e];
            if (s > v1)      { v2 = v1; i2 = i1; v1 = s; i1 = e; }
            else if (s > v2) { v2 = s; i2 = e; }
        }

        const int g = token0 + tid;
        const float inv = 1.0f / se;
        out[g * 2 + 0]        = (float)i1;
        out[g * 2 + 1]        = (float)i2;
        out[voff + g * 2 + 0] = __expf(v1 - m) * inv;
        out[voff + g * 2 + 1] = __expf(v2 - m) * inv;
    }
}

extern "C" void kernel_launch(void* const* d_in, const int* in_sizes, int n_in,
                              void* d_out, int out_size) {
    const float* x = (const float*)d_in[0];
    const float* W = (const float*)d_in[1];
    const float* b = (const float*)d_in[2];
    float* out = (float*)d_out;

    pack_w_kernel<<<(NE * NCH * 16 + 255) / 256, 256>>>(W);

    cudaFuncSetAttribute(gating_mma, cudaFuncAttributeMaxDynamicSharedMemorySize, SMEM_DYN);
    gating_mma<<<NTOK / BT, NTHR, SMEM_DYN>>>(x, b, out, out_size / 2);
}

// round 15
// speedup vs baseline: 1.5251x; 1.5251x over previous
#include <cuda_runtime.h>
#include <cuda_fp16.h>
#include <cstdint>
#include <math.h>

#define NTOK 16384
#define DIM  4096
#define NE   64
#define BT   64                   // tokens per CTA (M): 4 m16 stripes
#define KT   32                   // K per chunk (2 k16 halves, split across warps)
#define NCH  (DIM / KT)           // 128
#define NBUF 8
#define NTHR 512
// packed W tile: [arr 2][nhalf 2][qid 8][slot 16 x 4B x 4nt + 64B pad]
#define WQSTR  320
#define WARRB  (2 * 8 * WQSTR)    // 5120 per array
#define WBYTES (2 * WARRB)        // 10240 per chunk
#define SMEM_DYN (NBUF * WBYTES)  // 81920 (x2 CTAs = 160KB/SM)
#define SCSTR 66

static __device__ __forceinline__ uint32_t smem_u32(const void* p) {
    uint32_t a;
    asm("{ .reg .u64 t; cvta.to.shared.u64 t, %1; cvt.u32.u64 %0, t; }"
        : "=r"(a) : "l"(p));
    return a;
}
static __device__ __forceinline__ void cp16(uint32_t dst, const void* src) {
    asm volatile("cp.async.cg.shared.global [%0], [%1], 16;"
                 :: "r"(dst), "l"(src) : "memory");
}
#define CP_COMMIT() asm volatile("cp.async.commit_group;" ::: "memory")
#define CP_WAIT(n)  asm volatile("cp.async.wait_group %0;" :: "n"(n) : "memory")

// split: hi = rz-f16 pack (== mantissa-mask in normal range), lo = rz-f16(x - mask(x)).
static __device__ __forceinline__ void split_pair(float f0, float f1,
                                                  uint32_t& hi2, uint32_t& lo2) {
    asm("cvt.rz.f16x2.f32 %0, %1, %2;" : "=r"(hi2) : "f"(f1), "f"(f0));
    const float m0 = __uint_as_float(__float_as_uint(f0) & 0xffffe000u);
    const float m1 = __uint_as_float(__float_as_uint(f1) & 0xffffe000u);
    const float r0 = f0 - m0, r1 = f1 - m1;
    asm("cvt.rz.f16x2.f32 %0, %1, %2;" : "=r"(lo2) : "f"(r1), "f"(r0));
}
static __device__ __forceinline__ void mma16(float* c, const uint32_t* a,
                                             uint32_t b0, uint32_t b1) {
    asm volatile(
        "mma.sync.aligned.m16n8k16.row.col.f32.f16.f16.f32 "
        "{%0,%1,%2,%3}, {%4,%5,%6,%7}, {%8,%9}, {%0,%1,%2,%3};"
        : "+f"(c[0]), "+f"(c[1]), "+f"(c[2]), "+f"(c[3])
        : "r"(a[0]), "r"(a[1]), "r"(a[2]), "r"(a[3]), "r"(b0), "r"(b1));
}

// Packed, pre-split W with k-permutation matching the A direct-LDG layout:
// A lane (qid,qt,khalf) loads global k = 16*khalf + 4*qt + {0..3} as one LDG.128,
// mapping to a-regs {0,2} (row qid) / {1,3} (row qid+8). W slot for global pair
// g (k = 2g,2g+1 within chunk): h=g>>3, gm=g&7, qt=gm>>1, odd=gm&1 ->
// slot = 8h + qt + 4*odd, so b0 (slot 8h+qt) pairs with a0/a1 and b1 (slot+4)
// pairs with a2/a3. Dot product invariant under this shared permutation.
__device__ __align__(16) char g_wpack[NCH * WBYTES];

__global__ void pack_w_kernel(const float* __restrict__ W) {
    const int i = blockIdx.x * blockDim.x + threadIdx.x;   // 131072
    if (i >= NE * NCH * 16) return;
    const int g     = i & 15;                 // global k-pair within chunk
    const int chunk = (i >> 4) & (NCH - 1);
    const int e     = i >> 11;
    const int nhalf = e >> 5, rem = e & 31, nt = rem >> 3, qid = rem & 7;
    const int h = g >> 3, gm = g & 7, qtv = gm >> 1, odd = gm & 1;
    const int slot = 8 * h + qtv + 4 * odd;
    const int k0 = chunk * KT + 2 * g;
    const float w0 = W[(size_t)e * DIM + k0];
    const float w1 = W[(size_t)e * DIM + k0 + 1];
    const __half h0 = __float2half_rn(w0), h1 = __float2half_rn(w1);
    const __half l0 = __float2half_rn(w0 - __half2float(h0));
    const __half l1 = __float2half_rn(w1 - __half2float(h1));
    const uint32_t hi = ((uint32_t)__half_as_ushort(h1) << 16) | __half_as_ushort(h0);
    const uint32_t lo = ((uint32_t)__half_as_ushort(l1) << 16) | __half_as_ushort(l0);
    const uint32_t base = (uint32_t)chunk * WBYTES
                        + (uint32_t)(nhalf * 8 + qid) * WQSTR + slot * 16 + nt * 4;
    *(uint32_t*)(g_wpack + base)         = hi;
    *(uint32_t*)(g_wpack + base + WARRB) = lo;
}

__global__ __launch_bounds__(NTHR, 2)
void gating_mma(const float* __restrict__ X, const float* __restrict__ B,
                float* __restrict__ out, int voff)
{
    extern __shared__ char smem[];
    const int tid    = threadIdx.x;
    const int wid    = tid >> 5;
    const int lane   = tid & 31;
    const int qid    = lane >> 2;
    const int qt     = lane & 3;
    const int stripe = wid & 3;          // m16 stripe 0..3
    const int nhalf  = (wid >> 2) & 1;   // experts [nhalf*32, +32)
    const int khalf  = wid >> 3;         // k16 half within each chunk
    const int token0 = blockIdx.x * BT;

    const uint32_t sbase = smem_u32(smem);

    // ---- A direct-LDG pointers (row qid and qid+8 of this warp's stripe) ----
    const float* arow0 = X + (size_t)(token0 + stripe * 16 + qid) * DIM
                       + khalf * 16 + qt * 4;
    const float* arow1 = arow0 + (size_t)8 * DIM;

    // ---- W producer: 640 cp16 per chunk over 512 threads ----
    const char* wsrc0 = g_wpack + tid * 16;
    const char* wsrc1 = g_wpack + 8192 + tid * 16;
    auto cp_w = [&](int c) {
        const uint32_t bb = sbase + (uint32_t)(c & (NBUF - 1)) * WBYTES;
        cp16(bb + tid * 16, wsrc0 + (size_t)c * WBYTES);
        if (tid < 128) cp16(bb + 8192 + tid * 16, wsrc1 + (size_t)c * WBYTES);
    };

    float acc[4][4];
    #pragma unroll
    for (int nt = 0; nt < 4; nt++)
        #pragma unroll
        for (int j = 0; j < 4; j++) acc[nt][j] = 0.f;

    const uint32_t wlane = (uint32_t)(nhalf * 8 + qid) * WQSTR + (khalf * 8 + qt) * 16;

    // ---- prologue: A regs for chunks 0,1; W ring chunks 0..5 ----
    float4 xa0 = *(const float4*)(arow0);
    float4 xa1 = *(const float4*)(arow1);
    float4 xb0 = *(const float4*)(arow0 + KT);
    float4 xb1 = *(const float4*)(arow1 + KT);
    cp_w(0); CP_COMMIT();
    cp_w(1); CP_COMMIT();
    cp_w(2); CP_COMMIT();
    cp_w(3); CP_COMMIT();
    cp_w(4); CP_COMMIT();
    cp_w(5); CP_COMMIT();

    #pragma unroll 1
    for (int c = 0; c < NCH; c += 2) {
        CP_WAIT(4);
        __syncthreads();

        // ---------- chunk c (registers xa) ----------
        {
            uint32_t ah[4], al[4];
            split_pair(xa0.x, xa0.y, ah[0], al[0]);
            split_pair(xa1.x, xa1.y, ah[1], al[1]);
            split_pair(xa0.z, xa0.w, ah[2], al[2]);
            split_pair(xa1.z, xa1.w, ah[3], al[3]);
            if (c + 2 < NCH) {
                xa0 = *(const float4*)(arow0 + (c + 2) * KT);
                xa1 = *(const float4*)(arow1 + (c + 2) * KT);
            }
            const char* Wp = smem + (c & (NBUF - 1)) * WBYTES;
            const uint4 vh0 = *(const uint4*)(Wp + wlane);
            const uint4 vh1 = *(const uint4*)(Wp + wlane + 64);
            const uint4 vl0 = *(const uint4*)(Wp + wlane + WARRB);
            const uint4 vl1 = *(const uint4*)(Wp + wlane + WARRB + 64);
            const uint32_t bh0[4] = {vh0.x, vh0.y, vh0.z, vh0.w};
            const uint32_t bh1[4] = {vh1.x, vh1.y, vh1.z, vh1.w};
            const uint32_t bl0[4] = {vl0.x, vl0.y, vl0.z, vl0.w};
            const uint32_t bl1[4] = {vl1.x, vl1.y, vl1.z, vl1.w};
            #pragma unroll
            for (int nt = 0; nt < 4; nt++) mma16(acc[nt], ah, bh0[nt], bh1[nt]);
            #pragma unroll
            for (int nt = 0; nt < 4; nt++) mma16(acc[nt], ah, bl0[nt], bl1[nt]);
            #pragma unroll
            for (int nt = 0; nt < 4; nt++) mma16(acc[nt], al, bh0[nt], bh1[nt]);
        }

        // ---------- chunk c+1 (registers xb) ----------
        {
            uint32_t ah[4], al[4];
            split_pair(xb0.x, xb0.y, ah[0], al[0]);
            split_pair(xb1.x, xb1.y, ah[1], al[1]);
            split_pair(xb0.z, xb0.w, ah[2], al[2]);
            split_pair(xb1.z, xb1.w, ah[3], al[3]);
            if (c + 3 < NCH) {
                xb0 = *(const float4*)(arow0 + (c + 3) * KT);
                xb1 = *(const float4*)(arow1 + (c + 3) * KT);
            }
            const char* Wp = smem + ((c + 1) & (NBUF - 1)) * WBYTES;
            const uint4 vh0 = *(const uint4*)(Wp + wlane);
            const uint4 vh1 = *(const uint4*)(Wp + wlane + 64);
            const uint4 vl0 = *(const uint4*)(Wp + wlane + WARRB);
            const uint4 vl1 = *(const uint4*)(Wp + wlane + WARRB + 64);
            const uint32_t bh0[4] = {vh0.x, vh0.y, vh0.z, vh0.w};
            const uint32_t bh1[4] = {vh1.x, vh1.y, vh1.z, vh1.w};
            const uint32_t bl0[4] = {vl0.x, vl0.y, vl0.z, vl0.w};
            const uint32_t bl1[4] = {vl1.x, vl1.y, vl1.z, vl1.w};
            #pragma unroll
            for (int nt = 0; nt < 4; nt++) mma16(acc[nt], ah, bh0[nt], bh1[nt]);
            #pragma unroll
            for (int nt = 0; nt < 4; nt++) mma16(acc[nt], ah, bl0[nt], bl1[nt]);
            #pragma unroll
            for (int nt = 0; nt < 4; nt++) mma16(acc[nt], al, bh0[nt], bh1[nt]);
        }

        if (c + 6 < NCH) { cp_w(c + 6); CP_COMMIT(); }
        if (c + 7 < NCH) { cp_w(c + 7); CP_COMMIT(); }
    }

    CP_WAIT(0);
    __syncthreads();

    // ---- scores -> two smem banks (khalf partials), bias fused into bank 0 ----
    float* SC = (float*)smem;
    {
        float* SCk = SC + khalf * (BT * SCSTR);
        const int r0 = stripe * 16 + qid, r1 = r0 + 8;
        #pragma unroll
        for (int nt = 0; nt < 4; nt++) {
            const int cb = nhalf * 32 + nt * 8 + qt * 2;
            const float b0 = khalf ? 0.f : __ldg(B + cb);
            const float b1 = khalf ? 0.f : __ldg(B + cb + 1);
            *(float2*)(SCk + r0 * SCSTR + cb) = make_float2(acc[nt][0] + b0, acc[nt][1] + b1);
            *(float2*)(SCk + r1 * SCSTR + cb) = make_float2(acc[nt][2] + b0, acc[nt][3] + b1);
        }
    }
    __syncthreads();

    if (tid < BT) {
        const float* row0 = SC + tid * SCSTR;
        const float* row1 = row0 + BT * SCSTR;

        float sc[NE];
        #pragma unroll
        for (int e = 0; e < NE; e++) sc[e] = row0[e] + row1[e];

        float m = sc[0];
        #pragma unroll
        for (int e = 1; e < NE; e++) m = fmaxf(m, sc[e]);

        float se = 0.f;
        #pragma unroll
        for (int e = 0; e < NE; e++) se += __expf(sc[e] - m);

        float v1 = -1e30f, v2 = -1e30f; int i1 = -1, i2 = -1;
        #pragma unroll
        for (int e = 0; e < NE; e++) {
            const float s = sc[e];
            if (s > v1)      { v2 = v1; i2 = i1; v1 = s; i1 = e; }
            else if (s > v2) { v2 = s; i2 = e; }
        }

        const int g = token0 + tid;
        const float inv = 1.0f / se;
        out[g * 2 + 0]        = (float)i1;
        out[g * 2 + 1]        = (float)i2;
        out[voff + g * 2 + 0] = __expf(v1 - m) * inv;
        out[voff + g * 2 + 1] = __expf(v2 - m) * inv;
    }
}

extern "C" void kernel_launch(void* const* d_in, const int* in_sizes, int n_in,
                              void* d_out, int out_size) {
    const float* x = (const float*)d_in[0];
    const float* W = (const float*)d_in[1];
    const float* b = (const float*)d_in[2];
    float* out = (float*)d_out;

    pack_w_kernel<<<(NE * NCH * 16 + 255) / 256, 256>>>(W);

    cudaFuncSetAttribute(gating_mma, cudaFuncAttributeMaxDynamicSharedMemorySize, SMEM_DYN);
    gating_mma<<<NTOK / BT, NTHR, SMEM_DYN>>>(x, b, out, out_size / 2);
}